// round 1
// baseline (speedup 1.0000x reference)
#include <cuda_runtime.h>
#include <math.h>

#define Bn 2
#define Vn 8000
#define Fn 1500
#define Hn 128
#define Wn 128
#define NPIX (Bn * Hn * Wn)          // 32768
#define CHUNK 750                     // faces per smem chunk (2 chunks)

// Per-face record: 4 x float4
//  q0 = { x1, y1, A0=y2-y1, B0=x2-x1 }   (edge for w0, anchor v1)
//  q1 = { x2, y2, A1=y0-y2, B1=x0-x2 }   (edge for w1, anchor v2)
//  q2 = { x0, y0, A2=y1-y0, B2=x1-x0 }   (edge for w2, anchor v0)
//  q3 = { z0, z1, z2, inv_area (NaN if |area|<=1e-8) }
__device__ float4 g_faces[Bn * Fn * 4];

__global__ void setup_faces(const float* __restrict__ verts,
                            const float* __restrict__ R,
                            const float* __restrict__ T,
                            const float* __restrict__ focalp,
                            const int*   __restrict__ faces) {
    int t = blockIdx.x * blockDim.x + threadIdx.x;
    if (t >= Bn * Fn) return;
    int b = t / Fn;
    int f = t - b * Fn;
    float focal = focalp[0];
    const float* Rb = R + b * 9;
    const float* Tb = T + b * 3;

    float xs[3], ys[3], zs[3];
#pragma unroll
    for (int k = 0; k < 3; k++) {
        int vi = faces[f * 3 + k];
        const float* v = verts + ((long)b * Vn + vi) * 3;
        float vx = v[0], vy = v[1], vz = v[2];
        // vv_j = sum_i v_i * R[i][j] + T[j]
        float X = vx * Rb[0] + vy * Rb[3] + vz * Rb[6] + Tb[0];
        float Y = vx * Rb[1] + vy * Rb[4] + vz * Rb[7] + Tb[1];
        float Z = vx * Rb[2] + vy * Rb[5] + vz * Rb[8] + Tb[2];
        xs[k] = focal * X / Z;
        ys[k] = focal * Y / Z;
        zs[k] = Z;
    }

    // area = _edge(v0, v1, v2)
    float area = (xs[2] - xs[0]) * (ys[1] - ys[0]) - (ys[2] - ys[0]) * (xs[1] - xs[0]);
    float inv;
    if (fabsf(area) > 1e-8f) inv = 1.0f / area;
    else                     inv = __int_as_float(0x7fffffff);  // NaN: face can never win

    float4* dst = g_faces + t * 4;
    dst[0] = make_float4(xs[1], ys[1], ys[2] - ys[1], xs[2] - xs[1]);
    dst[1] = make_float4(xs[2], ys[2], ys[0] - ys[2], xs[0] - xs[2]);
    dst[2] = make_float4(xs[0], ys[0], ys[1] - ys[0], xs[1] - xs[0]);
    dst[3] = make_float4(zs[0], zs[1], zs[2], inv);
}

__device__ __forceinline__ float seg_d2(float ax, float ay, float dx, float dy,
                                        float px, float py) {
    float l2 = fmaxf(dx * dx + dy * dy, 1e-12f);
    float t  = ((px - ax) * dx + (py - ay) * dy) / l2;
    t = fminf(fmaxf(t, 0.0f), 1.0f);
    float ex = fmaf(t, dx, ax) - px;
    float ey = fmaf(t, dy, ay) - py;
    return ex * ex + ey * ey;
}

__global__ __launch_bounds__(256) void rasterize(float* __restrict__ out) {
    __shared__ float4 sf[CHUNK * 4];   // 48000 bytes

    int g = blockIdx.x * blockDim.x + threadIdx.x;   // 0..32767
    int b = g >> 14;
    int p = g & 16383;
    int i = p >> 7;          // row
    int j = p & 127;         // col
    float px = 1.0f - 2.0f * ((float)j + 0.5f) / 128.0f;
    float py = 1.0f - 2.0f * ((float)i + 0.5f) / 128.0f;

    float zmin = __int_as_float(0x7f800000);  // +inf
    int best = -1;

    for (int c = 0; c < 2; c++) {
        __syncthreads();
        const float4* src = g_faces + ((b * Fn + c * CHUNK) * 4);
        for (int k = threadIdx.x; k < CHUNK * 4; k += 256) sf[k] = src[k];
        __syncthreads();

        int base = c * CHUNK;
#pragma unroll 5
        for (int f = 0; f < CHUNK; f++) {
            float4 q0 = sf[f * 4 + 0];
            float4 q1 = sf[f * 4 + 1];
            float4 q2 = sf[f * 4 + 2];
            float4 q3 = sf[f * 4 + 3];
            float w0 = (px - q0.x) * q0.z - (py - q0.y) * q0.w;
            float w1 = (px - q1.x) * q1.z - (py - q1.y) * q1.w;
            float w2 = (px - q2.x) * q2.z - (py - q2.y) * q2.w;
            float inv = q3.w;
            float b0 = w0 * inv, b1 = w1 * inv, b2 = w2 * inv;
            float zp = fmaf(b2, q3.z, fmaf(b1, q3.y, b0 * q3.x));
            if (b0 >= 0.0f && b1 >= 0.0f && b2 >= 0.0f && zp > 1e-4f && zp < zmin) {
                zmin = zp;
                best = base + f;
            }
        }
    }

    float p2f = -1.0f, zb = -1.0f, c0o = -1.0f, c1o = -1.0f, c2o = -1.0f, dd = -1.0f;
    if (best >= 0) {
        const float4* fq = g_faces + ((b * Fn + best) * 4);
        float4 q0 = fq[0], q1 = fq[1], q2 = fq[2], q3 = fq[3];
        float w0 = (px - q0.x) * q0.z - (py - q0.y) * q0.w;
        float w1 = (px - q1.x) * q1.z - (py - q1.y) * q1.w;
        float w2 = (px - q2.x) * q2.z - (py - q2.y) * q2.w;
        float inv = q3.w;
        float c0 = w0 * inv, c1 = w1 * inv, c2 = w2 * inv;
        float zbest = fmaf(c2, q3.z, fmaf(c1, q3.y, c0 * q3.x));

        // edges: (v0->v1): a=v0=(q2.x,q2.y), d=(B2,A2)=(q2.w,q2.z)
        //        (v1->v2): a=v1=(q0.x,q0.y), d=(B0,A0)=(q0.w,q0.z)
        //        (v2->v0): a=v2=(q1.x,q1.y), d=(B1,A1)=(q1.w,q1.z)
        float d01 = seg_d2(q2.x, q2.y, q2.w, q2.z, px, py);
        float d12 = seg_d2(q0.x, q0.y, q0.w, q0.z, px, py);
        float d20 = seg_d2(q1.x, q1.y, q1.w, q1.z, px, py);
        float d2 = fminf(fminf(d01, d12), d20);
        bool insb = (c0 >= 0.0f) && (c1 >= 0.0f) && (c2 >= 0.0f);
        float dist = insb ? -d2 : d2;

        p2f = (float)best;
        zb = zbest;
        c0o = c0; c1o = c1; c2o = c2;
        dd = dist;
    }

    // outputs concatenated: p2f | zbuf | bary(3) | dists
    out[g]            = p2f;
    out[NPIX + g]     = zb;
    out[2 * NPIX + 3 * g + 0] = c0o;
    out[2 * NPIX + 3 * g + 1] = c1o;
    out[2 * NPIX + 3 * g + 2] = c2o;
    out[5 * NPIX + g] = dd;
}

extern "C" void kernel_launch(void* const* d_in, const int* in_sizes, int n_in,
                              void* d_out, int out_size) {
    const float* verts = (const float*)d_in[0];
    const float* R     = (const float*)d_in[1];
    const float* T     = (const float*)d_in[2];
    const float* focal = (const float*)d_in[3];
    const int*   faces = (const int*)d_in[4];
    float* out = (float*)d_out;

    setup_faces<<<(Bn * Fn + 255) / 256, 256>>>(verts, R, T, focal, faces);
    rasterize<<<NPIX / 256, 256>>>(out);
}

// round 3
// speedup vs baseline: 2.4106x; 2.4106x over previous
#include <cuda_runtime.h>
#include <math.h>

#define Bn 2
#define Vn 8000
#define Fn 1500
#define Hn 128
#define Wn 128
#define NPIX (Bn * Hn * Wn)          // 32768
#define NFACE (Bn * Fn)              // 3000

// Per-face record: 4 x float4
//  q0 = { x1, y1, A0=y2-y1, B0=x2-x1 }   (edge for w0, anchor v1)
//  q1 = { x2, y2, A1=y0-y2, B1=x0-x2 }   (edge for w1, anchor v2)
//  q2 = { x0, y0, A2=y1-y0, B2=x1-x0 }   (edge for w2, anchor v0)
//  q3 = { z0, z1, z2, inv_area (NaN if |area|<=1e-8) }
__device__ float4 g_faces[NFACE * 4];
__device__ unsigned long long g_zbuf[NPIX];

// Fused: init z-buffer (all 32768 threads) + project faces (first 3000 threads)
__global__ __launch_bounds__(256) void init_setup(const float* __restrict__ verts,
                                                  const float* __restrict__ R,
                                                  const float* __restrict__ T,
                                                  const float* __restrict__ focalp,
                                                  const int*   __restrict__ faces) {
    int t = blockIdx.x * blockDim.x + threadIdx.x;
    g_zbuf[t] = 0xFFFFFFFFFFFFFFFFull;
    if (t >= NFACE) return;

    int b = t / Fn;
    int f = t - b * Fn;
    float focal = focalp[0];
    const float* Rb = R + b * 9;
    const float* Tb = T + b * 3;

    float xs[3], ys[3], zs[3];
#pragma unroll
    for (int k = 0; k < 3; k++) {
        int vi = faces[f * 3 + k];
        const float* v = verts + ((long)b * Vn + vi) * 3;
        float vx = v[0], vy = v[1], vz = v[2];
        float X = vx * Rb[0] + vy * Rb[3] + vz * Rb[6] + Tb[0];
        float Y = vx * Rb[1] + vy * Rb[4] + vz * Rb[7] + Tb[1];
        float Z = vx * Rb[2] + vy * Rb[5] + vz * Rb[8] + Tb[2];
        xs[k] = focal * X / Z;
        ys[k] = focal * Y / Z;
        zs[k] = Z;
    }

    float area = (xs[2] - xs[0]) * (ys[1] - ys[0]) - (ys[2] - ys[0]) * (xs[1] - xs[0]);
    float inv;
    if (fabsf(area) > 1e-8f) inv = 1.0f / area;
    else                     inv = __int_as_float(0x7fffffff);  // NaN: never wins

    float4* dst = g_faces + t * 4;
    dst[0] = make_float4(xs[1], ys[1], ys[2] - ys[1], xs[2] - xs[1]);
    dst[1] = make_float4(xs[2], ys[2], ys[0] - ys[2], xs[0] - xs[2]);
    dst[2] = make_float4(xs[0], ys[0], ys[1] - ys[0], xs[1] - xs[0]);
    dst[3] = make_float4(zs[0], zs[1], zs[2], inv);
}

// One block per face: test only the face's screen bbox, atomicMin into z-buffer.
__global__ __launch_bounds__(128) void scatter() {
    int fb = blockIdx.x;              // 0..NFACE-1
    int b = fb / Fn;
    int fidx = fb - b * Fn;

    const float4* fq = g_faces + fb * 4;
    float4 q0 = fq[0], q1 = fq[1], q2 = fq[2], q3 = fq[3];
    float inv = q3.w;
    if (inv != inv) return;           // degenerate face

    // vertices: v1=(q0.x,q0.y) v2=(q1.x,q1.y) v0=(q2.x,q2.y)
    float xmn = fminf(fminf(q0.x, q1.x), q2.x);
    float xmx = fmaxf(fmaxf(q0.x, q1.x), q2.x);
    float ymn = fminf(fminf(q0.y, q1.y), q2.y);
    float ymx = fmaxf(fmaxf(q0.y, q1.y), q2.y);

    int jlo, jhi, ilo, ihi;
    if (isfinite(xmn) && isfinite(xmx) && isfinite(ymn) && isfinite(ymx)) {
        // px_j = 1 - 2(j+0.5)/128 decreasing in j ; need xmn<=px_j<=xmx
        float a = fminf(fmaxf((1.0f - xmx) * 64.0f - 0.5f, -1e9f), 1e9f);
        float c = fminf(fmaxf((1.0f - xmn) * 64.0f - 0.5f, -1e9f), 1e9f);
        float d = fminf(fmaxf((1.0f - ymx) * 64.0f - 0.5f, -1e9f), 1e9f);
        float e = fminf(fmaxf((1.0f - ymn) * 64.0f - 0.5f, -1e9f), 1e9f);
        jlo = max(0,   (int)floorf(a) - 1);
        jhi = min(127, (int)ceilf(c)  + 1);
        ilo = max(0,   (int)floorf(d) - 1);
        ihi = min(127, (int)ceilf(e)  + 1);
    } else {
        jlo = 0; jhi = 127; ilo = 0; ihi = 127;  // conservative fallback
    }
    if (jlo > jhi || ilo > ihi) return;

    int cols = jhi - jlo + 1;
    int total = (ihi - ilo + 1) * cols;
    unsigned long long tag = ((unsigned long long)0) | (unsigned)fidx;
    int base = b << 14;

    for (int k = threadIdx.x; k < total; k += 128) {
        int i = ilo + k / cols;
        int j = jlo + k - (k / cols) * cols;
        float px = 1.0f - 2.0f * ((float)j + 0.5f) * (1.0f / 128.0f);
        float py = 1.0f - 2.0f * ((float)i + 0.5f) * (1.0f / 128.0f);

        float w0 = (px - q0.x) * q0.z - (py - q0.y) * q0.w;
        float w1 = (px - q1.x) * q1.z - (py - q1.y) * q1.w;
        float w2 = (px - q2.x) * q2.z - (py - q2.y) * q2.w;
        float b0 = w0 * inv, b1 = w1 * inv, b2 = w2 * inv;
        float zp = fmaf(b2, q3.z, fmaf(b1, q3.y, b0 * q3.x));
        if (b0 >= 0.0f && b1 >= 0.0f && b2 >= 0.0f && zp > 1e-4f) {
            unsigned long long pack =
                ((unsigned long long)__float_as_uint(zp) << 32) | tag;
            atomicMin(&g_zbuf[base + (i << 7) + j], pack);
        }
    }
}

__device__ __forceinline__ float seg_d2(float ax, float ay, float dx, float dy,
                                        float px, float py) {
    float l2 = fmaxf(dx * dx + dy * dy, 1e-12f);
    float t  = ((px - ax) * dx + (py - ay) * dy) / l2;
    t = fminf(fmaxf(t, 0.0f), 1.0f);
    float ex = fmaf(t, dx, ax) - px;
    float ey = fmaf(t, dy, ay) - py;
    return ex * ex + ey * ey;
}

__global__ __launch_bounds__(256) void resolve(float* __restrict__ out) {
    int g = blockIdx.x * blockDim.x + threadIdx.x;   // 0..NPIX-1
    int b = g >> 14;
    int p = g & 16383;
    int i = p >> 7;
    int j = p & 127;
    float px = 1.0f - 2.0f * ((float)j + 0.5f) * (1.0f / 128.0f);
    float py = 1.0f - 2.0f * ((float)i + 0.5f) * (1.0f / 128.0f);

    unsigned long long packed = g_zbuf[g];

    float p2f = -1.0f, zb = -1.0f, c0o = -1.0f, c1o = -1.0f, c2o = -1.0f, dd = -1.0f;
    if (packed != 0xFFFFFFFFFFFFFFFFull) {
        int best = (int)(unsigned)(packed & 0xFFFFFFFFull);
        const float4* fq = g_faces + ((b * Fn + best) * 4);
        float4 q0 = fq[0], q1 = fq[1], q2 = fq[2], q3 = fq[3];
        float w0 = (px - q0.x) * q0.z - (py - q0.y) * q0.w;
        float w1 = (px - q1.x) * q1.z - (py - q1.y) * q1.w;
        float w2 = (px - q2.x) * q2.z - (py - q2.y) * q2.w;
        float inv = q3.w;
        float c0 = w0 * inv, c1 = w1 * inv, c2 = w2 * inv;
        float zbest = fmaf(c2, q3.z, fmaf(c1, q3.y, c0 * q3.x));

        float d01 = seg_d2(q2.x, q2.y, q2.w, q2.z, px, py);
        float d12 = seg_d2(q0.x, q0.y, q0.w, q0.z, px, py);
        float d20 = seg_d2(q1.x, q1.y, q1.w, q1.z, px, py);
        float d2 = fminf(fminf(d01, d12), d20);
        bool insb = (c0 >= 0.0f) && (c1 >= 0.0f) && (c2 >= 0.0f);
        float dist = insb ? -d2 : d2;

        p2f = (float)best;
        zb = zbest;
        c0o = c0; c1o = c1; c2o = c2;
        dd = dist;
    }

    out[g]        = p2f;
    out[NPIX + g] = zb;
    out[2 * NPIX + 3 * g + 0] = c0o;
    out[2 * NPIX + 3 * g + 1] = c1o;
    out[2 * NPIX + 3 * g + 2] = c2o;
    out[5 * NPIX + g] = dd;
}

extern "C" void kernel_launch(void* const* d_in, const int* in_sizes, int n_in,
                              void* d_out, int out_size) {
    const float* verts = (const float*)d_in[0];
    const float* R     = (const float*)d_in[1];
    const float* T     = (const float*)d_in[2];
    const float* focal = (const float*)d_in[3];
    const int*   faces = (const int*)d_in[4];
    float* out = (float*)d_out;

    init_setup<<<NPIX / 256, 256>>>(verts, R, T, focal, faces);
    scatter<<<NFACE, 128>>>();
    resolve<<<NPIX / 256, 256>>>(out);
}